// round 15
// baseline (speedup 1.0000x reference)
#include <cuda_runtime.h>

// fusedmax(x) = sparsemax(prox_TV1D(x, alpha=1)), row-wise. B=4096, N=512, fp32.
// 128 blocks x 32 threads; lane = row. ys stride-32 (bank = lane), transposes
// via padded staging tile. Condat scan split hot/end (R12 structure); all hot
// indices carried as BYTE offsets (element=128B, seg entry=256B) so address
// arithmetic is pure IADD. RLE log -> Michelot sparsemax -> rebuild.

#define NROWS 4096
#define NCOLS 512
#define ROWS_PER_BLK 32
#define PADS 33
#define YS_FLOATS (NCOLS * 32)
#define STAGE_FLOATS (32 * PADS)
#define SEG_ENTRIES 517
#define SEG_OFF (YS_FLOATS + STAGE_FLOATS)
#define SMEM_BYTES ((SEG_OFF) * 4 + SEG_ENTRIES * 32 * 8)
#define ELT 128                         // bytes per element step (stride-32 f32)
#define LIM ((NCOLS - 1) * ELT)         // byte offset of element n-1

typedef unsigned long long ull;

__device__ __forceinline__ float frcp_fast(float a) {
    float r;
    asm("rcp.approx.f32 %0, %1;" : "=f"(r) : "f"(a));
    return r;
}

__global__ __launch_bounds__(32, 1)
void fusedmax_kernel(const float* __restrict__ x, float* __restrict__ out) {
    extern __shared__ float smem[];
    float* ys    = smem;                         // [NCOLS][32], stride 32
    float* stage = smem + YS_FLOATS;             // [32][PADS] (also overrun pad)
    ull*   segb  = (ull*)(smem + SEG_OFF);       // [entry][lane]

    const int lane    = threadIdx.x;
    const int rowBase = blockIdx.x * ROWS_PER_BLK;
    const float lam   = 1.0f;
    const int n       = NCOLS;

    // ---- load + transpose via staging tile (both sides conflict-free) ----
    const float* src = x + (size_t)rowBase * NCOLS;
    for (int t = 0; t < 16; t++) {
        #pragma unroll
        for (int i = 0; i < 32; i++)
            stage[i * PADS + lane] = src[i * NCOLS + t * 32 + lane];
        __syncwarp();
        #pragma unroll
        for (int cl = 0; cl < 32; cl++)
            ys[(t * 32 + cl) * 32 + lane] = stage[lane * PADS + cl];
        __syncwarp();
    }

    const char* ylb = (const char*)(ys + lane);  // y[c] at ylb + c*ELT
    char*       sgb = (char*)(segb + lane);      // entry j at sgb + j*256
    float*      yl  = ys + lane;

    // ---- Condat TV1D: hot loop (byte-offset indices) + end step ----
    int   k_b = 0, km_b = 0, kp_b = 0;           // byte offsets
    float vmin = yl[0] - lam;
    float vmax = vmin + 2.0f * lam;
    float umin = lam, umax = -lam;
    float thr_n = (vmin - umin) - lam;           // neg-jump threshold
    float thr_p = (vmax - umax) + lam;           // pos-jump threshold
    float cnt_f = 1.0f;
    float yn = *(const float*)(ylb + ELT);       // y[k+1]
    int   nseg_b = 0;                            // byte offset into seg log

    while (true) {
        // -------- hot scan: no end-phase logic --------
        while (k_b < LIM) {
            const float inv_spec = frcp_fast(cnt_f + 1.0f);
            const float ycur = yn;               // y[k+1]

            const bool neg  = (ycur < thr_n);
            const bool pos  = (!neg) & (ycur > thr_p);
            const bool jump = neg | pos;

            const int nk_b = (neg ? km_b : (pos ? kp_b : k_b)) + ELT;
            // nk_b <= LIM guaranteed (k_b <= LIM-ELT, km_b,kp_b <= k_b)

            const float ynk = *(const float*)(ylb + nk_b);
            yn = *(const float*)(ylb + nk_b + ELT);   // nk_b==LIM reads stage:
                                                      // dead value
            // RLE log: predicated store, byte bump on jump
            if (jump) {
                *(ull*)(sgb + nseg_b) =
                    ((ull)(unsigned)((neg ? km_b : kp_b) >> 7) << 32) |
                    (ull)__float_as_uint(pos ? vmax : vmin);
            }
            nseg_b += jump ? 256 : 0;

            // mid candidates (register-fed)
            const float inv_cnt = jump ? 1.0f : inv_spec;
            const float umin_t  = umin + ycur - vmin;
            const float umax_t  = umax + ycur - vmax;
            const bool  c1 = (umin_t >= lam);
            const bool  c2 = (umax_t <= -lam);
            const float vmin_mid = c1 ? fmaf(umin_t - lam, inv_cnt, vmin) : vmin;
            const float umin_mid = c1 ? lam : umin_t;
            const int   km_mid   = c1 ? nk_b : km_b;
            const float vmax_mid = c2 ? fmaf(umax_t + lam, inv_cnt, vmax) : vmax;
            const float umax_mid = c2 ? -lam : umax_t;
            const int   kp_mid   = c2 ? nk_b : kp_b;

            // merge (interior jump: full reset, no end-phase cases)
            vmin = jump ? (neg ? ynk : ynk - 2.0f * lam) : vmin_mid;
            vmax = jump ? (pos ? ynk : ynk + 2.0f * lam) : vmax_mid;
            umin = jump ? lam  : umin_mid;
            umax = jump ? -lam : umax_mid;
            km_b = jump ? nk_b : km_mid;
            kp_b = jump ? nk_b : kp_mid;
            cnt_f = jump ? 1.0f : (cnt_f + 1.0f);
            k_b  = nk_b;
            thr_n = (vmin - umin) - lam;         // off-chain
            thr_p = (vmax - umax) + lam;
        }

        // -------- end step: k == n-1 --------
        if (umin < 0.0f) {                       // negative end jump
            *(ull*)(sgb + nseg_b) = ((ull)(unsigned)(km_b >> 7) << 32) |
                                    (ull)__float_as_uint(vmin);
            nseg_b += 256;
            const int nk_b = min(km_b + ELT, LIM);
            const float ynk = *(const float*)(ylb + nk_b);
            yn = *(const float*)(ylb + min(nk_b + ELT, LIM));
            k_b = km_b = nk_b;                   // kp, vmax unchanged
            vmin = ynk;
            umin = lam;
            umax = ynk + lam - vmax;
            cnt_f = 1.0f;
            thr_n = (vmin - umin) - lam;
            thr_p = (vmax - umax) + lam;
        } else if (umax > 0.0f) {                // positive end jump
            *(ull*)(sgb + nseg_b) = ((ull)(unsigned)(kp_b >> 7) << 32) |
                                    (ull)__float_as_uint(vmax);
            nseg_b += 256;
            const int nk_b = min(kp_b + ELT, LIM);
            const float ynk = *(const float*)(ylb + nk_b);
            yn = *(const float*)(ylb + min(nk_b + ELT, LIM));
            k_b = kp_b = nk_b;                   // km, vmin unchanged
            vmax = ynk;
            umax = -lam;
            umin = ynk - lam - vmin;
            cnt_f = 1.0f;
            thr_n = (vmin - umin) - lam;
            thr_p = (vmax - umax) + lam;
        } else {                                 // finished
            *(ull*)(sgb + nseg_b) = ((ull)(unsigned)(n - 1) << 32) |
                (ull)__float_as_uint(fmaf(umin, frcp_fast(cnt_f), vmin));
            nseg_b += 256;
            break;
        }
    }

    // ---- sparsemax tau via Michelot on the RLE segments ----
    float tau;
    {
        float sum = 0.0f;
        int prev = -1;
        for (int jb = 0; jb < nseg_b; jb += 256) {
            ull w = *(const ull*)(sgb + jb);
            int e = (int)(w >> 32);
            sum += (float)(e - prev) * __uint_as_float((unsigned)w);
            prev = e;
        }
        tau = (sum - 1.0f) * (1.0f / (float)NCOLS);
        int c_prev = n;
        for (int it = 0; it < n; it++) {
            float s = 0.0f;
            int   c = 0;
            int   pr = -1;
            for (int jb = 0; jb < nseg_b; jb += 256) {
                ull   w = *(const ull*)(sgb + jb);
                int   e = (int)(w >> 32);
                float v = __uint_as_float((unsigned)w);
                int len = e - pr; pr = e;
                bool sup = (v > tau);
                s += sup ? (float)len * v : 0.0f;
                c += sup ? len : 0;
            }
            if (c == c_prev) break;
            tau = (s - 1.0f) / (float)c;
            c_prev = c;
        }
    }

    // ---- reconstruct max(val - tau, 0) into ys (prefetched walk) ----
    {
        int jb = 0;
        ull w  = *(const ull*)(sgb);
        ull wn = *(const ull*)(sgb + 256);
        int   e = (int)(w >> 32);
        float v = __uint_as_float((unsigned)w) - tau;
        for (int c = 0; c < n; c++) {
            yl[c * 32] = fmaxf(v, 0.0f);
            const bool adv = ((c + 1) > e);
            jb += adv ? 256 : 0;
            w = adv ? wn : w;
            e = (int)(w >> 32);
            v = __uint_as_float((unsigned)w) - tau;
            wn = *(const ull*)(sgb + min(jb + 256, (SEG_ENTRIES - 1) * 256));
        }
    }
    __syncwarp();

    // ---- transpose back via staging + coalesced store ----
    float* dst = out + (size_t)rowBase * NCOLS;
    for (int t = 0; t < 16; t++) {
        #pragma unroll
        for (int cl = 0; cl < 32; cl++)
            stage[lane * PADS + cl] = ys[(t * 32 + cl) * 32 + lane];
        __syncwarp();
        #pragma unroll
        for (int i = 0; i < 32; i++)
            dst[i * NCOLS + t * 32 + lane] = stage[i * PADS + lane];
        __syncwarp();
    }
}

extern "C" void kernel_launch(void* const* d_in, const int* in_sizes, int n_in,
                              void* d_out, int out_size) {
    (void)in_sizes; (void)n_in; (void)out_size;
    const float* x   = (const float*)d_in[0];
    float*       out = (float*)d_out;

    cudaFuncSetAttribute(fusedmax_kernel,
                         cudaFuncAttributeMaxDynamicSharedMemorySize,
                         SMEM_BYTES);
    fusedmax_kernel<<<NROWS / ROWS_PER_BLK, ROWS_PER_BLK, SMEM_BYTES>>>(x, out);
}

// round 16
// speedup vs baseline: 1.5827x; 1.5827x over previous
#include <cuda_runtime.h>

// fusedmax(x) = sparsemax(prox_TV1D(x, alpha=1)), row-wise. B=4096, N=512, fp32.
// 128 blocks x 32 threads; lane = row. ys stride-32 (bank = lane), transposes
// via padded staging tile. Condat scan split hot/end (R12 champion structure);
// folded merge selects; dead inv_cnt select removed.
// RLE log -> Michelot sparsemax -> prefetched rebuild.

#define NROWS 4096
#define NCOLS 512
#define ROWS_PER_BLK 32
#define PADS 33
#define YS_FLOATS (NCOLS * 32)
#define STAGE_FLOATS (32 * PADS)
#define SEG_ENTRIES 517
#define SEG_OFF (YS_FLOATS + STAGE_FLOATS)
#define SMEM_BYTES ((SEG_OFF) * 4 + SEG_ENTRIES * 32 * 8)

typedef unsigned long long ull;

__device__ __forceinline__ float frcp_fast(float a) {
    float r;
    asm("rcp.approx.f32 %0, %1;" : "=f"(r) : "f"(a));
    return r;
}

__global__ __launch_bounds__(32, 1)
void fusedmax_kernel(const float* __restrict__ x, float* __restrict__ out) {
    extern __shared__ float smem[];
    float* ys    = smem;                         // [NCOLS][32], stride 32
    float* stage = smem + YS_FLOATS;             // [32][PADS] (also overrun pad)
    ull*   segb  = (ull*)(smem + SEG_OFF);       // [entry][lane]

    const int lane    = threadIdx.x;
    const int rowBase = blockIdx.x * ROWS_PER_BLK;
    const float lam   = 1.0f;
    const int n       = NCOLS;

    // ---- load + transpose via staging tile (both sides conflict-free) ----
    const float* src = x + (size_t)rowBase * NCOLS;
    for (int t = 0; t < 16; t++) {
        #pragma unroll
        for (int i = 0; i < 32; i++)
            stage[i * PADS + lane] = src[i * NCOLS + t * 32 + lane];
        __syncwarp();
        #pragma unroll
        for (int cl = 0; cl < 32; cl++)
            ys[(t * 32 + cl) * 32 + lane] = stage[lane * PADS + cl];
        __syncwarp();
    }

    float* yl   = ys + lane;                     // yl[c*32] == y[c], bank=lane
    ull*   segl = segb + lane;

    // ---- Condat TV1D: hot loop (k < n-1) + end step (k == n-1) ----
    int   k = 0, km = 0, kp = 0;
    float vmin = yl[0] - lam;
    float vmax = vmin + 2.0f * lam;
    float umin = lam, umax = -lam;
    float thr_n = (vmin - umin) - lam;           // neg-jump threshold
    float thr_p = (vmax - umax) + lam;           // pos-jump threshold
    float cnt_f = 1.0f;
    float yn = yl[1 * 32];                       // y[k+1]
    int   nseg = 0;

    while (true) {
        // -------- hot scan: no end-phase logic --------
        while (k < n - 1) {
            const float inv_spec = frcp_fast(cnt_f + 1.0f);
            const float ycur = yn;               // y[k+1]

            const bool neg  = (ycur < thr_n);
            const bool pos  = (!neg) & (ycur > thr_p);
            const bool jump = neg | pos;

            const int nk = neg ? (km + 1) : (pos ? (kp + 1) : (k + 1));
            // nk <= n-1 guaranteed (k <= n-2, km,kp <= k)

            const float ynk = yl[nk * 32];       // == ycur for mid lanes
            yn = yl[(nk + 1) * 32];              // prefetch (nk+1==n reads
                                                 // stage[lane]: dead value)

            // RLE log: predicated store, bump on jump
            if (jump) {
                segl[nseg * 32] =
                    ((ull)(unsigned)(neg ? km : kp) << 32) |
                    (ull)__float_as_uint(pos ? vmax : vmin);
            }
            nseg += (int)jump;

            // mid candidates (inv_spec garbage-tolerant: discarded on jump)
            const float umin_t  = umin + ycur - vmin;
            const float umax_t  = umax + ycur - vmax;
            const bool  c1 = (umin_t >= lam);
            const bool  c2 = (umax_t <= -lam);
            const bool  p1 = jump | c1;
            const bool  p2 = jump | c2;
            const float vmin_mid = c1 ? fmaf(umin_t - lam, inv_spec, vmin) : vmin;
            const float vmax_mid = c2 ? fmaf(umax_t + lam, inv_spec, vmax) : vmax;

            // merge (folded selects; interior jump: full reset)
            vmin = jump ? (neg ? ynk : ynk - 2.0f * lam) : vmin_mid;
            vmax = jump ? (pos ? ynk : ynk + 2.0f * lam) : vmax_mid;
            umin = p1 ? lam  : umin_t;
            umax = p2 ? -lam : umax_t;
            km   = p1 ? nk : km;
            kp   = p2 ? nk : kp;
            cnt_f = jump ? 1.0f : (cnt_f + 1.0f);
            k    = nk;
            thr_n = (vmin - umin) - lam;         // off-chain
            thr_p = (vmax - umax) + lam;
        }

        // -------- end step: k == n-1 --------
        if (umin < 0.0f) {                       // negative end jump
            segl[nseg * 32] = ((ull)(unsigned)km << 32) |
                              (ull)__float_as_uint(vmin);
            nseg++;
            const int nk = min(km + 1, n - 1);
            const float ynk = yl[nk * 32];
            yn = yl[min(nk + 1, n - 1) * 32];
            k = km = nk;                         // kp, vmax unchanged
            vmin = ynk;
            umin = lam;
            umax = ynk + lam - vmax;
            cnt_f = 1.0f;
            thr_n = (vmin - umin) - lam;
            thr_p = (vmax - umax) + lam;
        } else if (umax > 0.0f) {                // positive end jump
            segl[nseg * 32] = ((ull)(unsigned)kp << 32) |
                              (ull)__float_as_uint(vmax);
            nseg++;
            const int nk = min(kp + 1, n - 1);
            const float ynk = yl[nk * 32];
            yn = yl[min(nk + 1, n - 1) * 32];
            k = kp = nk;                         // km, vmin unchanged
            vmax = ynk;
            umax = -lam;
            umin = ynk - lam - vmin;
            cnt_f = 1.0f;
            thr_n = (vmin - umin) - lam;
            thr_p = (vmax - umax) + lam;
        } else {                                 // finished
            segl[nseg * 32] = ((ull)(unsigned)(n - 1) << 32) |
                (ull)__float_as_uint(fmaf(umin, frcp_fast(cnt_f), vmin));
            nseg++;
            break;
        }
    }

    // ---- sparsemax tau via Michelot on the RLE segments ----
    float tau;
    {
        float sum = 0.0f;
        int prev = -1;
        for (int j = 0; j < nseg; j++) {
            ull w = segl[j * 32];
            int e = (int)(w >> 32);
            sum += (float)(e - prev) * __uint_as_float((unsigned)w);
            prev = e;
        }
        tau = (sum - 1.0f) * (1.0f / (float)NCOLS);
        int c_prev = n;
        for (int it = 0; it < n; it++) {
            float s = 0.0f;
            int   c = 0;
            int   pr = -1;
            for (int j = 0; j < nseg; j++) {
                ull   w = segl[j * 32];
                int   e = (int)(w >> 32);
                float v = __uint_as_float((unsigned)w);
                int len = e - pr; pr = e;
                bool sup = (v > tau);
                s += sup ? (float)len * v : 0.0f;
                c += sup ? len : 0;
            }
            if (c == c_prev) break;
            tau = (s - 1.0f) / (float)c;
            c_prev = c;
        }
    }

    // ---- reconstruct max(val - tau, 0) into ys (prefetched walk) ----
    {
        int j = 0;
        ull w  = segl[0];
        ull wn = segl[32];
        int   e = (int)(w >> 32);
        float v = __uint_as_float((unsigned)w) - tau;
        for (int c = 0; c < n; c++) {
            yl[c * 32] = fmaxf(v, 0.0f);
            const bool adv = ((c + 1) > e);
            j += (int)adv;
            w = adv ? wn : w;
            e = (int)(w >> 32);
            v = __uint_as_float((unsigned)w) - tau;
            wn = segl[min(j + 1, SEG_ENTRIES - 1) * 32];
        }
    }
    __syncwarp();

    // ---- transpose back via staging + coalesced store ----
    float* dst = out + (size_t)rowBase * NCOLS;
    for (int t = 0; t < 16; t++) {
        #pragma unroll
        for (int cl = 0; cl < 32; cl++)
            stage[lane * PADS + cl] = ys[(t * 32 + cl) * 32 + lane];
        __syncwarp();
        #pragma unroll
        for (int i = 0; i < 32; i++)
            dst[i * NCOLS + t * 32 + lane] = stage[i * PADS + lane];
        __syncwarp();
    }
}

extern "C" void kernel_launch(void* const* d_in, const int* in_sizes, int n_in,
                              void* d_out, int out_size) {
    (void)in_sizes; (void)n_in; (void)out_size;
    const float* x   = (const float*)d_in[0];
    float*       out = (float*)d_out;

    cudaFuncSetAttribute(fusedmax_kernel,
                         cudaFuncAttributeMaxDynamicSharedMemorySize,
                         SMEM_BYTES);
    fusedmax_kernel<<<NROWS / ROWS_PER_BLK, ROWS_PER_BLK, SMEM_BYTES>>>(x, out);
}